// round 6
// baseline (speedup 1.0000x reference)
#include <cuda_runtime.h>

#define NN 50000
#define NE 800000
#define F0 100
#define F1 256
#define F2 128

// ---------------- scratch (static device globals; no allocations) ----------
__device__ __align__(16) float d_dinv[NN];                 // deg then rsqrt(deg)
__device__ __align__(16) float d_g1[(size_t)NN * F1];      // dinv-scaled h1
__device__ __align__(16) float d_agg1[(size_t)NN * F1];    // scatter target (init = g1)
__device__ __align__(16) float d_relu1[(size_t)NN * F1];   // layer-1 activation
__device__ __align__(16) float d_g2[(size_t)NN * F2];
__device__ __align__(16) float d_agg2[(size_t)NN * F2];

// ---------------- degree / normalization ----------------------------------
__global__ void k_init_deg() {
    int i = blockIdx.x * blockDim.x + threadIdx.x;
    if (i < NN) d_dinv[i] = 1.0f;   // self-loop contributes 1
}

__global__ void k_edge_deg(const int* __restrict__ dst) {
    int e = blockIdx.x * blockDim.x + threadIdx.x;
    if (e < NE) {
        int d = dst[e];
        if (d >= 0 && d < NN) atomicAdd(&d_dinv[d], 1.0f);
    }
}

__global__ void k_rsqrt() {
    int i = blockIdx.x * blockDim.x + threadIdx.x;
    if (i < NN) d_dinv[i] = rsqrtf(d_dinv[i]);
}

// ---------------- SGEMM with fused row-scaling epilogue --------------------
// C[r,c] = dinv[r] * sum_k A[r,k] B[k,c]; written to both G and AGG.
// Layer L selects A (layer 2 reads d_relu1) and the scratch outputs in device
// code — no __device__ symbol ever touched from host code.
#define BM 64
#define BN 64
#define BK 16

template <int L>
__global__ void k_gemm_scale(const float* __restrict__ Ain, const float* __restrict__ B,
                             int M, int N, int K) {
    const float* __restrict__ A = (L == 1) ? Ain : d_relu1;
    float* __restrict__ G   = (L == 1) ? d_g1   : d_g2;
    float* __restrict__ AGG = (L == 1) ? d_agg1 : d_agg2;

    __shared__ float As[BK][BM + 1];
    __shared__ float Bs[BK][BN];
    int tid = threadIdx.x;
    int tx = tid & 15, ty = tid >> 4;
    int rowBase = blockIdx.y * BM;
    int colBase = blockIdx.x * BN;
    float acc[4][4] = {};

    for (int k0 = 0; k0 < K; k0 += BK) {
        #pragma unroll
        for (int i = tid; i < BM * BK; i += 256) {
            int r = i >> 4, c = i & 15;
            int gr = rowBase + r, gc = k0 + c;
            As[c][r] = (gr < M && gc < K) ? A[(size_t)gr * K + gc] : 0.0f;
        }
        #pragma unroll
        for (int i = tid; i < BK * BN; i += 256) {
            int r = i >> 6, c = i & 63;
            int gr = k0 + r, gc = colBase + c;
            Bs[r][c] = (gr < K && gc < N) ? B[(size_t)gr * N + gc] : 0.0f;
        }
        __syncthreads();
        #pragma unroll
        for (int k = 0; k < BK; k++) {
            float a[4], b[4];
            #pragma unroll
            for (int i = 0; i < 4; i++) a[i] = As[k][ty * 4 + i];
            #pragma unroll
            for (int j = 0; j < 4; j++) b[j] = Bs[k][tx * 4 + j];
            #pragma unroll
            for (int i = 0; i < 4; i++)
                #pragma unroll
                for (int j = 0; j < 4; j++) acc[i][j] += a[i] * b[j];
        }
        __syncthreads();
    }

    #pragma unroll
    for (int i = 0; i < 4; i++) {
        int r = rowBase + ty * 4 + i;
        if (r >= M) continue;
        float s = d_dinv[r];
        #pragma unroll
        for (int j = 0; j < 4; j++) {
            int c = colBase + tx * 4 + j;
            if (c < N) {
                float v = acc[i][j] * s;
                G[(size_t)r * N + c] = v;
                AGG[(size_t)r * N + c] = v;   // self-loop term pre-seeded
            }
        }
    }
}

// ---------------- edge scatter: AGG[dst] += G[src] -------------------------
// One warp per edge; float4 reads, scalar atomic adds.
template <int L>
__global__ void k_scatter(const int* __restrict__ src,
                          const int* __restrict__ dst) {
    const float* __restrict__ G   = (L == 1) ? d_g1   : d_g2;
    float* __restrict__ AGG       = (L == 1) ? d_agg1 : d_agg2;
    const int F  = (L == 1) ? F1 : F2;
    const int F4 = F / 4;

    int w = (blockIdx.x * blockDim.x + threadIdx.x) >> 5;
    int lane = threadIdx.x & 31;
    if (w >= NE) return;
    int s = src[w], d = dst[w];
    if ((unsigned)s >= NN || (unsigned)d >= NN) return;
    const float4* grow = (const float4*)(G + (size_t)s * F);
    float* arow = AGG + (size_t)d * F;
    #pragma unroll
    for (int j = lane; j < F4; j += 32) {
        float4 v = grow[j];
        atomicAdd(arow + 4 * j + 0, v.x);
        atomicAdd(arow + 4 * j + 1, v.y);
        atomicAdd(arow + 4 * j + 2, v.z);
        atomicAdd(arow + 4 * j + 3, v.w);
    }
}

// ---------------- finalize layer 1: relu(dinv*agg + b) ---------------------
__global__ void k_finalize1(const float* __restrict__ b1) {
    size_t idx = (size_t)blockIdx.x * blockDim.x + threadIdx.x;  // float4 index
    const size_t total = (size_t)NN * (F1 / 4);
    if (idx >= total) return;
    int r = (int)(idx / (F1 / 4));
    int c4 = (int)(idx % (F1 / 4));
    float s = d_dinv[r];
    float4 a = ((const float4*)d_agg1)[idx];
    float4 bb = ((const float4*)b1)[c4];
    float4 o;
    o.x = fmaxf(fmaf(a.x, s, bb.x), 0.0f);
    o.y = fmaxf(fmaf(a.y, s, bb.y), 0.0f);
    o.z = fmaxf(fmaf(a.z, s, bb.z), 0.0f);
    o.w = fmaxf(fmaf(a.w, s, bb.w), 0.0f);
    ((float4*)d_relu1)[idx] = o;
}

// ---------------- finalize layer 2 fused with FC head ----------------------
// out[i] = dot(relu(dinv[i]*agg2[i,:] + b2), Wfc) + bfc ; warp per node.
__global__ void k_fc(const float* __restrict__ b2, const float* __restrict__ Wfc,
                     const float* __restrict__ bfc, float* __restrict__ out) {
    int w = (blockIdx.x * blockDim.x + threadIdx.x) >> 5;
    int lane = threadIdx.x & 31;
    if (w >= NN) return;
    float s = d_dinv[w];
    float4 a = ((const float4*)(d_agg2 + (size_t)w * F2))[lane];  // F2/4 == 32
    float4 bb = ((const float4*)b2)[lane];
    float4 wf = ((const float4*)Wfc)[lane];
    float acc = fmaxf(fmaf(a.x, s, bb.x), 0.0f) * wf.x
              + fmaxf(fmaf(a.y, s, bb.y), 0.0f) * wf.y
              + fmaxf(fmaf(a.z, s, bb.z), 0.0f) * wf.z
              + fmaxf(fmaf(a.w, s, bb.w), 0.0f) * wf.w;
    #pragma unroll
    for (int o = 16; o > 0; o >>= 1) acc += __shfl_down_sync(0xffffffffu, acc, o);
    if (lane == 0) out[w] = acc + bfc[0];
}

// ---------------- launch ----------------------------------------------------
extern "C" void kernel_launch(void* const* d_in, const int* in_sizes, int n_in,
                              void* d_out, int out_size) {
    const float* x   = (const float*)d_in[0];
    const int*   ei  = (const int*)d_in[1];    // [2, NE] int32 (JAX x64 disabled)
    const float* W1  = (const float*)d_in[2];
    const float* b1  = (const float*)d_in[3];
    const float* W2  = (const float*)d_in[4];
    const float* b2  = (const float*)d_in[5];
    const float* Wfc = (const float*)d_in[6];
    const float* bfc = (const float*)d_in[7];
    float* out = (float*)d_out;

    const int* src = ei;
    const int* dst = ei + NE;

    // degree + normalization
    k_init_deg<<<(NN + 255) / 256, 256>>>();
    k_edge_deg<<<(NE + 255) / 256, 256>>>(dst);
    k_rsqrt<<<(NN + 255) / 256, 256>>>();

    // layer 1
    {
        dim3 grid(F1 / BN, (NN + BM - 1) / BM);
        k_gemm_scale<1><<<grid, 256>>>(x, W1, NN, F1, F0);
    }
    k_scatter<1><<<(NE * 32 + 255) / 256, 256>>>(src, dst);
    k_finalize1<<<((NN * (F1 / 4)) + 255) / 256, 256>>>(b1);

    // layer 2 (A = d_relu1 selected inside the kernel)
    {
        dim3 grid(F2 / BN, (NN + BM - 1) / BM);
        k_gemm_scale<2><<<grid, 256>>>(nullptr, W2, NN, F2, F1);
    }
    k_scatter<2><<<(NE * 32 + 255) / 256, 256>>>(src, dst);

    // finalize layer 2 + FC head
    k_fc<<<(NN * 32 + 255) / 256, 256>>>(b2, Wfc, bfc, out);
}

// round 7
// speedup vs baseline: 2.1424x; 2.1424x over previous
#include <cuda_runtime.h>

#define NN 50000
#define NE 800000
#define F0 100
#define F1 256
#define F2 128

// ---------------- scratch (static device globals; no allocations) ----------
__device__ __align__(16) float d_dinv[NN];                 // deg then rsqrt(deg)
__device__ __align__(16) float d_g0[(size_t)NN * F0];      // dinv-scaled x
__device__ __align__(16) float d_agg0[(size_t)NN * F0];    // layer-1 aggregation (init = g0)
__device__ __align__(16) float d_relu1[(size_t)NN * F1];   // layer-1 activation
__device__ __align__(16) float d_g2[(size_t)NN * F2];
__device__ __align__(16) float d_agg2[(size_t)NN * F2];

// ---------------- degree / normalization ----------------------------------
__global__ void k_init_deg() {
    int i = blockIdx.x * blockDim.x + threadIdx.x;
    if (i < NN) d_dinv[i] = 1.0f;   // self-loop contributes 1
}

__global__ void k_edge_deg(const int* __restrict__ dst) {
    int e = blockIdx.x * blockDim.x + threadIdx.x;
    if (e < NE) {
        int d = dst[e];
        if (d >= 0 && d < NN) atomicAdd(&d_dinv[d], 1.0f);
    }
}

__global__ void k_rsqrt() {
    int i = blockIdx.x * blockDim.x + threadIdx.x;
    if (i < NN) d_dinv[i] = rsqrtf(d_dinv[i]);
}

// ---------------- layer-1 pre-scale: g0 = agg0 = dinv[r] * x ---------------
__global__ void k_scale0(const float* __restrict__ x) {
    const int R4 = F0 / 4;                       // 25 float4 per row
    size_t idx = (size_t)blockIdx.x * blockDim.x + threadIdx.x;
    const size_t total = (size_t)NN * R4;
    if (idx >= total) return;
    int r = (int)(idx / R4);
    float s = d_dinv[r];
    float4 v = ((const float4*)x)[idx];
    v.x *= s; v.y *= s; v.z *= s; v.w *= s;
    ((float4*)d_g0)[idx] = v;
    ((float4*)d_agg0)[idx] = v;                  // self-loop term pre-seeded
}

// ---------------- edge scatter with vector red.global ----------------------
__device__ __forceinline__ void red_add_v4(float* p, float4 v) {
    asm volatile("red.global.add.v4.f32 [%0], {%1, %2, %3, %4};"
                 :: "l"(p), "f"(v.x), "f"(v.y), "f"(v.z), "f"(v.w)
                 : "memory");
}

template <int L>
__global__ void k_scatter(const int* __restrict__ src,
                          const int* __restrict__ dst) {
    const float* __restrict__ G   = (L == 1) ? d_g0   : d_g2;
    float* __restrict__ AGG       = (L == 1) ? d_agg0 : d_agg2;
    const int F  = (L == 1) ? F0 : F2;
    const int F4 = F / 4;                        // 25 or 32

    int w = (blockIdx.x * blockDim.x + threadIdx.x) >> 5;
    int lane = threadIdx.x & 31;
    if (w >= NE) return;
    int s = src[w], d = dst[w];
    if ((unsigned)s >= NN || (unsigned)d >= NN) return;
    if (lane < F4) {
        float4 v = ((const float4*)(G + (size_t)s * F))[lane];
        red_add_v4(AGG + (size_t)d * F + 4 * lane, v);
    }
}

// ---------------- SGEMM, BM=128 x BN=64 x BK=16, 8x4 per thread ------------
// L==1: A = dinv[r]*agg0 (scaled at load), C = relu(acc + b1) -> d_relu1
// L==2: A = d_relu1,                       C = dinv[r]*acc -> d_g2 and d_agg2
#define BM 128
#define BN 64
#define BK 16

template <int L>
__global__ void k_gemm_impl(const float* __restrict__ B,
                            const float* __restrict__ bias,
                            int M, int N, int K) {
    const float* __restrict__ A = (L == 1) ? d_agg0 : d_relu1;

    __shared__ float As[BK][BM + 4];
    __shared__ float Bs[BK][BN];
    int tid = threadIdx.x;
    int tx = tid & 15, ty = tid >> 4;
    int rowBase = blockIdx.y * BM;
    int colBase = blockIdx.x * BN;
    float acc[8][4] = {};

    for (int k0 = 0; k0 < K; k0 += BK) {
        #pragma unroll
        for (int i = tid; i < BM * BK; i += 256) {
            int r = i >> 4, c = i & 15;
            int gr = rowBase + r, gc = k0 + c;
            float v = (gr < M && gc < K) ? A[(size_t)gr * K + gc] : 0.0f;
            if (L == 1 && gr < M) v *= d_dinv[gr];   // fold dinv into A
            As[c][r] = v;
        }
        #pragma unroll
        for (int i = tid; i < BK * BN; i += 256) {
            int r = i >> 6, c = i & 63;
            int gr = k0 + r, gc = colBase + c;
            Bs[r][c] = (gr < K && gc < N) ? B[(size_t)gr * N + gc] : 0.0f;
        }
        __syncthreads();
        #pragma unroll
        for (int k = 0; k < BK; k++) {
            float a[8], b[4];
            #pragma unroll
            for (int i = 0; i < 8; i++) a[i] = As[k][ty * 8 + i];
            #pragma unroll
            for (int j = 0; j < 4; j++) b[j] = Bs[k][tx * 4 + j];
            #pragma unroll
            for (int i = 0; i < 8; i++)
                #pragma unroll
                for (int j = 0; j < 4; j++) acc[i][j] += a[i] * b[j];
        }
        __syncthreads();
    }

    #pragma unroll
    for (int i = 0; i < 8; i++) {
        int r = rowBase + ty * 8 + i;
        if (r >= M) continue;
        if (L == 1) {
            #pragma unroll
            for (int j = 0; j < 4; j++) {
                int c = colBase + tx * 4 + j;
                d_relu1[(size_t)r * N + c] = fmaxf(acc[i][j] + bias[c], 0.0f);
            }
        } else {
            float s = d_dinv[r];
            #pragma unroll
            for (int j = 0; j < 4; j++) {
                int c = colBase + tx * 4 + j;
                float v = acc[i][j] * s;
                d_g2[(size_t)r * N + c] = v;
                d_agg2[(size_t)r * N + c] = v;   // self-loop term pre-seeded
            }
        }
    }
}

// ---------------- finalize layer 2 fused with FC head ----------------------
__global__ void k_fc(const float* __restrict__ b2, const float* __restrict__ Wfc,
                     const float* __restrict__ bfc, float* __restrict__ out) {
    int w = (blockIdx.x * blockDim.x + threadIdx.x) >> 5;
    int lane = threadIdx.x & 31;
    if (w >= NN) return;
    float s = d_dinv[w];
    float4 a = ((const float4*)(d_agg2 + (size_t)w * F2))[lane];  // F2/4 == 32
    float4 bb = ((const float4*)b2)[lane];
    float4 wf = ((const float4*)Wfc)[lane];
    float acc = fmaxf(fmaf(a.x, s, bb.x), 0.0f) * wf.x
              + fmaxf(fmaf(a.y, s, bb.y), 0.0f) * wf.y
              + fmaxf(fmaf(a.z, s, bb.z), 0.0f) * wf.z
              + fmaxf(fmaf(a.w, s, bb.w), 0.0f) * wf.w;
    #pragma unroll
    for (int o = 16; o > 0; o >>= 1) acc += __shfl_down_sync(0xffffffffu, acc, o);
    if (lane == 0) out[w] = acc + bfc[0];
}

// ---------------- launch ----------------------------------------------------
extern "C" void kernel_launch(void* const* d_in, const int* in_sizes, int n_in,
                              void* d_out, int out_size) {
    const float* x   = (const float*)d_in[0];
    const int*   ei  = (const int*)d_in[1];    // [2, NE] int32 (JAX x64 disabled)
    const float* W1  = (const float*)d_in[2];
    const float* b1  = (const float*)d_in[3];
    const float* W2  = (const float*)d_in[4];
    const float* b2  = (const float*)d_in[5];
    const float* Wfc = (const float*)d_in[6];
    const float* bfc = (const float*)d_in[7];
    float* out = (float*)d_out;

    const int* src = ei;
    const int* dst = ei + NE;

    // degree + normalization
    k_init_deg<<<(NN + 255) / 256, 256>>>();
    k_edge_deg<<<(NE + 255) / 256, 256>>>(dst);
    k_rsqrt<<<(NN + 255) / 256, 256>>>();

    // layer 1: aggregate x (F=100) first, then GEMM with fused relu+bias
    k_scale0<<<((NN * (F0 / 4)) + 255) / 256, 256>>>(x);
    k_scatter<1><<<(NE * 32 + 255) / 256, 256>>>(src, dst);
    {
        dim3 grid(F1 / BN, (NN + BM - 1) / BM);
        k_gemm_impl<1><<<grid, 256>>>(W1, b1, NN, F1, F0);
    }

    // layer 2: GEMM (seeds agg2), then aggregate h2 (F=128)
    {
        dim3 grid(F2 / BN, (NN + BM - 1) / BM);
        k_gemm_impl<2><<<grid, 256>>>(W2, nullptr, NN, F2, F1);
    }
    k_scatter<2><<<(NE * 32 + 255) / 256, 256>>>(src, dst);

    // finalize layer 2 + FC head
    k_fc<<<(NN * 32 + 255) / 256, 256>>>(b2, Wfc, bfc, out);
}